// round 9
// baseline (speedup 1.0000x reference)
#include <cuda_runtime.h>
#include <math.h>

#define NB_   1024
#define NS    500
#define RG    128
#define NLAT  12
#define NFEAT 64
#define NHID  128
#define NPTS  (NB_*NS)
#define NROW  21          // 9 raw inputs + 12 folded latents

// Scratch (static device arrays: no allocation allowed)
__device__ float4 g_rgbs[NPTS];          // (r, g, b, sdf) - only active entries written
__device__ float  g_W1eff[NLAT*NHID];    // folded Wf @ W1[9:73]
__device__ float  g_b1eff[NHID];         // b1 + bf @ W1[9:73]
__device__ int    g_act_list[NPTS];      // packed (ray<<9)|s for active samples
__device__ int    g_slo[NB_];            // first active s per ray
__device__ int    g_scnt[NB_];           // active count per ray
__device__ int    g_total;               // total active samples

// ---------------------------------------------------------------------------
__global__ __launch_bounds__(256)
void prep_kernel(const float* __restrict__ Wf,
                 const float* __restrict__ bf,
                 const float* __restrict__ W1,
                 const float* __restrict__ b1)
{
    int tid = threadIdx.x;
    if (tid == 0) g_total = 0;
    for (int e = tid; e < NLAT*NHID; e += 256) {
        int l = e >> 7, j = e & 127;
        float acc = 0.f;
        #pragma unroll 8
        for (int f = 0; f < NFEAT; f++)
            acc = fmaf(Wf[l*NFEAT + f], W1[(9+f)*NHID + j], acc);
        g_W1eff[e] = acc;
    }
    for (int j = tid; j < NHID; j += 256) {
        float acc = b1[j];
        #pragma unroll 8
        for (int f = 0; f < NFEAT; f++)
            acc = fmaf(bf[f], W1[(9+f)*NHID + j], acc);
        g_b1eff[j] = acc;
    }
}

__global__ void noop_kernel() {}

// ---------------------------------------------------------------------------
// interval_kernel: one warp per ray. Per-sample in-box mask (exact same
// arithmetic as the reference), ballot -> contiguous [first,last], compact.
// ---------------------------------------------------------------------------
__global__ __launch_bounds__(256)
void interval_kernel(const float* __restrict__ rays_o,
                     const float* __restrict__ rays_d)
{
    int warp = (blockIdx.x*blockDim.x + threadIdx.x) >> 5;
    int lane = threadIdx.x & 31;
    if (warp >= NB_) return;
    int ray = warp;

    float ox = __ldg(&rays_o[3*ray+0]), oy = __ldg(&rays_o[3*ray+1]),
          oz = __ldg(&rays_o[3*ray+2]);
    float dx = __ldg(&rays_d[3*ray+0]), dy = __ldg(&rays_d[3*ray+1]),
          dz = __ldg(&rays_d[3*ray+2]);

    int first = -1, last = -1;
    #pragma unroll
    for (int c = 0; c < 16; c++) {
        int s = c*32 + lane;
        float z  = 0.5f + 3.0f*((float)s * (1.0f/499.0f));
        float px = fmaf(dx, z, ox), py = fmaf(dy, z, oy), pz = fmaf(dz, z, oz);
        bool act = (s < NS) &
                   (px >= -1.f) & (px <= 1.f) &
                   (py >= -1.f) & (py <= 1.f) &
                   (pz >= -1.f) & (pz <= 1.f);
        unsigned m = __ballot_sync(0xffffffffu, act);
        if (m) {
            if (first < 0) first = c*32 + (__ffs(m) - 1);
            last = c*32 + (31 - __clz(m));
        }
    }
    int cnt = (first >= 0) ? (last - first + 1) : 0;

    int off = 0;
    if (lane == 0) {
        g_slo[ray]  = first;
        g_scnt[ray] = cnt;
        if (cnt > 0) off = atomicAdd(&g_total, cnt);
    }
    off = __shfl_sync(0xffffffffu, off, 0);

    if (cnt > 0) {
        for (int s = first + lane; s <= last; s += 32)
            g_act_list[off + (s - first)] = (ray << 9) | s;
    }
}

// ---------------------------------------------------------------------------
// trilerp helper: returns vals[13] + grad of channel 0; assumes in-box point
// ---------------------------------------------------------------------------
__device__ __forceinline__ void trilerp13(const float* __restrict__ grid,
                                          float px, float py, float pz,
                                          float* __restrict__ vals,
                                          float& gx, float& gy, float& gz)
{
    const int OX = RG*RG*13, OY = RG*13, OZ = 13;
    float ux = (px + 1.f)*63.5f, uy = (py + 1.f)*63.5f, uz = (pz + 1.f)*63.5f;
    int ix = min((int)ux, 126), iy = min((int)uy, 126), iz = min((int)uz, 126);
    float fx = ux - (float)ix, fy = uy - (float)iy, fz = uz - (float)iz;
    float wx0 = 1.f-fx, wx1 = fx, wy0 = 1.f-fy, wy1 = fy, wz0 = 1.f-fz, wz1 = fz;

    const float* gp = grid + ((size_t)(ix*RG + iy)*RG + iz)*13;

    #pragma unroll
    for (int c = 0; c < 13; c++) vals[c] = 0.f;
    float c0a[8];
    #pragma unroll
    for (int cc = 0; cc < 8; cc++) {
        int dx = cc >> 2, dy = (cc >> 1) & 1, dz = cc & 1;
        const float* p = gp + dx*OX + dy*OY + dz*OZ;
        float w = (dx ? wx1 : wx0) * (dy ? wy1 : wy0) * (dz ? wz1 : wz0);
        float v0 = __ldg(p);
        c0a[cc] = v0;
        vals[0] = fmaf(w, v0, vals[0]);
        #pragma unroll
        for (int c = 1; c < 13; c++) vals[c] = fmaf(w, __ldg(p + c), vals[c]);
    }
    gx = 63.5f*( wy0*wz0*(c0a[4]-c0a[0]) + wy0*wz1*(c0a[5]-c0a[1])
               + wy1*wz0*(c0a[6]-c0a[2]) + wy1*wz1*(c0a[7]-c0a[3]) );
    gy = 63.5f*( wx0*wz0*(c0a[2]-c0a[0]) + wx0*wz1*(c0a[3]-c0a[1])
               + wx1*wz0*(c0a[6]-c0a[4]) + wx1*wz1*(c0a[7]-c0a[5]) );
    gz = 63.5f*( wx0*wy0*(c0a[1]-c0a[0]) + wx0*wy1*(c0a[3]-c0a[2])
               + wx1*wy0*(c0a[5]-c0a[4]) + wx1*wy1*(c0a[7]-c0a[6]) );
}

// ---------------------------------------------------------------------------
// Kernel A: dense list of active samples; ONE sample per thread, high occ.
// ---------------------------------------------------------------------------
__global__ __launch_bounds__(128, 5)
void point_kernel(const float* __restrict__ rays_o,
                  const float* __restrict__ rays_d,
                  const float* __restrict__ viewdirs,
                  const float* __restrict__ grid,
                  const float* __restrict__ W1,
                  const float* __restrict__ W2,
                  const float* __restrict__ b2)
{
    __shared__ __align__(16) float sW[NROW*NHID];  // rows 0-8 raw, 9-20 folded
    __shared__ __align__(16) float sW2t[3*NHID];   // [c][j]
    __shared__ __align__(16) float sb1[NHID];
    __shared__ float sb2[4];

    for (int i = threadIdx.x; i < 9*NHID; i += blockDim.x) sW[i] = W1[i];
    for (int i = threadIdx.x; i < NLAT*NHID; i += blockDim.x)
        sW[9*NHID + i] = g_W1eff[i];
    for (int i = threadIdx.x; i < NHID; i += blockDim.x) sb1[i] = g_b1eff[i];
    for (int i = threadIdx.x; i < NHID*3; i += blockDim.x) {
        int j = i / 3, c = i - 3*j;
        sW2t[c*NHID + j] = W2[i];
    }
    if (threadIdx.x < 3) sb2[threadIdx.x] = b2[threadIdx.x];
    __syncthreads();

    int total  = g_total;
    int gid    = blockIdx.x*blockDim.x + threadIdx.x;
    int stride = gridDim.x*blockDim.x;

    for (int i = gid; i < total; i += stride) {
        int ia = g_act_list[i];
        int r = ia >> 9, s = ia & 511;

        float z  = 0.5f + 3.0f*((float)s * (1.0f/499.0f));
        float px = fmaf(__ldg(&rays_d[3*r+0]), z, __ldg(&rays_o[3*r+0]));
        float py = fmaf(__ldg(&rays_d[3*r+1]), z, __ldg(&rays_o[3*r+1]));
        float pz = fmaf(__ldg(&rays_d[3*r+2]), z, __ldg(&rays_o[3*r+2]));

        float vals[13], gx, gy, gz;
        trilerp13(grid, px, py, pz, vals, gx, gy, gz);

        float in[NROW];
        in[0]=px; in[1]=py; in[2]=pz; in[3]=gx; in[4]=gy; in[5]=gz;
        in[6]=__ldg(&viewdirs[3*r+0]);
        in[7]=__ldg(&viewdirs[3*r+1]);
        in[8]=__ldg(&viewdirs[3*r+2]);
        #pragma unroll
        for (int l = 0; l < NLAT; l++) in[9+l] = vals[1+l];

        float o0=0.f, o1=0.f, o2=0.f;
        #pragma unroll 4
        for (int j = 0; j < NHID; j += 4) {
            float4 acc = *(const float4*)&sb1[j];
            #pragma unroll
            for (int k = 0; k < NROW; k++) {
                float4 w = *(const float4*)&sW[k*NHID + j];
                float hk = in[k];
                acc.x = fmaf(hk, w.x, acc.x);
                acc.y = fmaf(hk, w.y, acc.y);
                acc.z = fmaf(hk, w.z, acc.z);
                acc.w = fmaf(hk, w.w, acc.w);
            }
            acc.x = fmaxf(acc.x, 0.f); acc.y = fmaxf(acc.y, 0.f);
            acc.z = fmaxf(acc.z, 0.f); acc.w = fmaxf(acc.w, 0.f);
            float4 wa = *(const float4*)&sW2t[0*NHID + j];
            float4 wb = *(const float4*)&sW2t[1*NHID + j];
            float4 wc = *(const float4*)&sW2t[2*NHID + j];
            o0 = fmaf(acc.x,wa.x, fmaf(acc.y,wa.y, fmaf(acc.z,wa.z, fmaf(acc.w,wa.w, o0))));
            o1 = fmaf(acc.x,wb.x, fmaf(acc.y,wb.y, fmaf(acc.z,wb.z, fmaf(acc.w,wb.w, o1))));
            o2 = fmaf(acc.x,wc.x, fmaf(acc.y,wc.y, fmaf(acc.z,wc.z, fmaf(acc.w,wc.w, o2))));
        }
        o0 += sb2[0]; o1 += sb2[1]; o2 += sb2[2];

        g_rgbs[r*NS + s] = make_float4(1.f/(1.f + expf(-o0)),
                                       1.f/(1.f + expf(-o1)),
                                       1.f/(1.f + expf(-o2)), vals[0]);
    }
}

// ---------------------------------------------------------------------------
// Kernel B: per-ray transmittance scan. One warp (=one block) per ray.
// Out-of-interval samples use the sentinel (0,0,0,100) without loading.
// ---------------------------------------------------------------------------
__global__ __launch_bounds__(32)
void ray_kernel(const float* __restrict__ rays_d,
                const float* __restrict__ beta_p,
                float* __restrict__ out)
{
    int ray  = blockIdx.x;
    int lane = threadIdx.x;

    float be    = fabsf(__ldg(beta_p)) + 1e-4f;
    float inv_b = 1.0f / be;
    float d0 = __ldg(&rays_d[3*ray+0]);
    float d1 = __ldg(&rays_d[3*ray+1]);
    float d2 = __ldg(&rays_d[3*ray+2]);
    float dn = sqrtf(d0*d0 + d1*d1 + d2*d2);

    int slo = g_slo[ray];
    int scnt = g_scnt[ray];
    int shi = slo + scnt;   // exclusive; slo = -1, scnt = 0 if empty

    const float4* vp = g_rgbs + (size_t)ray*NS;
    const float dist = 3.0f/499.0f;

    float4 v[16];
    #pragma unroll
    for (int c = 0; c < 16; c++) {
        int s = c*32 + lane;
        bool in = (scnt > 0) & (s >= slo) & (s < shi) & (s < NS);
        v[c] = in ? __ldg(&vp[s]) : make_float4(0.f, 0.f, 0.f, 100.f);
    }

    float fe[16];
    #pragma unroll
    for (int c = 0; c < 16; c++) {
        float sdf = v[c].w;
        float as  = fabsf(sdf);
        float sg  = (sdf > 0.f) ? 1.f : ((sdf < 0.f) ? -1.f : 0.f);
        float dens = inv_b * (0.5f + 0.5f*sg*expm1f(-as*inv_b));
        fe[c] = dist * dens;
    }

    float inc[16];
    #pragma unroll
    for (int c = 0; c < 16; c++) {
        float x = fe[c];
        #pragma unroll
        for (int o = 1; o < 32; o <<= 1) {
            float n = __shfl_up_sync(0xffffffffu, x, o);
            if (lane >= o) x += n;
        }
        inc[c] = x;
    }

    float carry = 0.f, r0 = 0.f, r1 = 0.f, r2 = 0.f, dep = 0.f;
    #pragma unroll
    for (int c = 0; c < 16; c++) {
        float excl  = carry + (inc[c] - fe[c]);
        float T     = expf(-excl);
        float alpha = 1.f - expf(-fe[c]);
        float w     = alpha * T;
        int   s     = c*32 + lane;
        float zs    = 0.5f + 3.0f*((float)s * (1.0f/499.0f));
        if (s < NS) {
            r0  += w * v[c].x;
            r1  += w * v[c].y;
            r2  += w * v[c].z;
            dep += w * zs * dn;
        }
        carry += __shfl_sync(0xffffffffu, inc[c], 31);
    }

    #pragma unroll
    for (int o = 16; o > 0; o >>= 1) {
        r0  += __shfl_xor_sync(0xffffffffu, r0,  o);
        r1  += __shfl_xor_sync(0xffffffffu, r1,  o);
        r2  += __shfl_xor_sync(0xffffffffu, r2,  o);
        dep += __shfl_xor_sync(0xffffffffu, dep, o);
    }
    if (lane == 0) {
        out[3*ray+0]     = r0;
        out[3*ray+1]     = r1;
        out[3*ray+2]     = r2;
        out[3*NB_ + ray] = dep;
    }
}

// ---------------------------------------------------------------------------
extern "C" void kernel_launch(void* const* d_in, const int* in_sizes, int n_in,
                              void* d_out, int out_size)
{
    const float* rays_o   = (const float*)d_in[0];
    const float* rays_d   = (const float*)d_in[1];
    const float* viewdirs = (const float*)d_in[2];
    const float* grid     = (const float*)d_in[3];
    const float* Wf       = (const float*)d_in[4];
    const float* bf       = (const float*)d_in[5];
    const float* W1       = (const float*)d_in[6];
    const float* b1       = (const float*)d_in[7];
    const float* W2       = (const float*)d_in[8];
    const float* b2       = (const float*)d_in[9];
    const float* beta     = (const float*)d_in[10];

    // ncu captures our 0-based launch index 3 -> point_kernel there.
    prep_kernel<<<1, 256>>>(Wf, bf, W1, b1);                 // also resets g_total
    interval_kernel<<<NB_/8, 256>>>(rays_o, rays_d);         // 1024 warps
    noop_kernel<<<1, 32>>>();
    point_kernel<<<740, 128>>>(rays_o, rays_d, viewdirs, grid, W1, W2, b2);
    ray_kernel<<<NB_, 32>>>(rays_d, beta, (float*)d_out);
}

// round 10
// speedup vs baseline: 1.0005x; 1.0005x over previous
#include <cuda_runtime.h>
#include <math.h>

#define NB_   1024
#define NS    500
#define RG    128
#define NLAT  12
#define NFEAT 64
#define NHID  128
#define NPTS  (NB_*NS)
#define NROW  21          // 9 raw inputs + 12 folded latents

// Scratch (static device arrays: no allocation allowed)
__device__ float4 g_rgbs[NPTS];          // (r, g, b, sdf) - active entries only
__device__ float  g_W1eff[NLAT*NHID];    // folded Wf @ W1[9:73]
__device__ float  g_b1eff[NHID];         // b1 + bf @ W1[9:73]
__device__ int    g_act_list[NPTS];      // packed (ray<<9)|s for active samples
__device__ int    g_slo[NB_];            // first active s per ray
__device__ int    g_scnt[NB_];           // active count per ray
__device__ int    g_total;               // total active samples
__device__ float  g_inT[22*NPTS];        // transposed MLP inputs: [k][i], k=21 is sdf

// ---------------------------------------------------------------------------
__global__ __launch_bounds__(256)
void prep_kernel(const float* __restrict__ Wf,
                 const float* __restrict__ bf,
                 const float* __restrict__ W1,
                 const float* __restrict__ b1)
{
    int tid = threadIdx.x;
    if (tid == 0) g_total = 0;
    for (int e = tid; e < NLAT*NHID; e += 256) {
        int l = e >> 7, j = e & 127;
        float acc = 0.f;
        #pragma unroll 8
        for (int f = 0; f < NFEAT; f++)
            acc = fmaf(Wf[l*NFEAT + f], W1[(9+f)*NHID + j], acc);
        g_W1eff[e] = acc;
    }
    for (int j = tid; j < NHID; j += 256) {
        float acc = b1[j];
        #pragma unroll 8
        for (int f = 0; f < NFEAT; f++)
            acc = fmaf(bf[f], W1[(9+f)*NHID + j], acc);
        g_b1eff[j] = acc;
    }
}

// ---------------------------------------------------------------------------
// interval_kernel: one warp per ray; ballot -> contiguous [first,last], compact.
// ---------------------------------------------------------------------------
__global__ __launch_bounds__(256)
void interval_kernel(const float* __restrict__ rays_o,
                     const float* __restrict__ rays_d)
{
    int warp = (blockIdx.x*blockDim.x + threadIdx.x) >> 5;
    int lane = threadIdx.x & 31;
    if (warp >= NB_) return;
    int ray = warp;

    float ox = __ldg(&rays_o[3*ray+0]), oy = __ldg(&rays_o[3*ray+1]),
          oz = __ldg(&rays_o[3*ray+2]);
    float dx = __ldg(&rays_d[3*ray+0]), dy = __ldg(&rays_d[3*ray+1]),
          dz = __ldg(&rays_d[3*ray+2]);

    int first = -1, last = -1;
    #pragma unroll
    for (int c = 0; c < 16; c++) {
        int s = c*32 + lane;
        float z  = 0.5f + 3.0f*((float)s * (1.0f/499.0f));
        float px = fmaf(dx, z, ox), py = fmaf(dy, z, oy), pz = fmaf(dz, z, oz);
        bool act = (s < NS) &
                   (px >= -1.f) & (px <= 1.f) &
                   (py >= -1.f) & (py <= 1.f) &
                   (pz >= -1.f) & (pz <= 1.f);
        unsigned m = __ballot_sync(0xffffffffu, act);
        if (m) {
            if (first < 0) first = c*32 + (__ffs(m) - 1);
            last = c*32 + (31 - __clz(m));
        }
    }
    int cnt = (first >= 0) ? (last - first + 1) : 0;

    int off = 0;
    if (lane == 0) {
        g_slo[ray]  = first;
        g_scnt[ray] = cnt;
        if (cnt > 0) off = atomicAdd(&g_total, cnt);
    }
    off = __shfl_sync(0xffffffffu, off, 0);

    if (cnt > 0) {
        for (int s = first + lane; s <= last; s += 32)
            g_act_list[off + (s - first)] = (ray << 9) | s;
    }
}

// ---------------------------------------------------------------------------
// Kernel T: trilerp + grad, one point per thread, HIGH occupancy.
// Writes transposed inputs g_inT[k][i] (coalesced per k) + sdf at k=21.
// ---------------------------------------------------------------------------
__global__ __launch_bounds__(128, 8)
void trilerp_kernel(const float* __restrict__ rays_o,
                    const float* __restrict__ rays_d,
                    const float* __restrict__ viewdirs,
                    const float* __restrict__ grid)
{
    const int OX = RG*RG*13, OY = RG*13, OZ = 13;
    int total  = g_total;
    int gid    = blockIdx.x*blockDim.x + threadIdx.x;
    int stride = gridDim.x*blockDim.x;

    for (int i = gid; i < total; i += stride) {
        int ia = g_act_list[i];
        int r = ia >> 9, s = ia & 511;

        float z  = 0.5f + 3.0f*((float)s * (1.0f/499.0f));
        float px = fmaf(__ldg(&rays_d[3*r+0]), z, __ldg(&rays_o[3*r+0]));
        float py = fmaf(__ldg(&rays_d[3*r+1]), z, __ldg(&rays_o[3*r+1]));
        float pz = fmaf(__ldg(&rays_d[3*r+2]), z, __ldg(&rays_o[3*r+2]));

        float ux = (px + 1.f)*63.5f, uy = (py + 1.f)*63.5f, uz = (pz + 1.f)*63.5f;
        int ix = min((int)ux, 126), iy = min((int)uy, 126), iz = min((int)uz, 126);
        float fx = ux - (float)ix, fy = uy - (float)iy, fz = uz - (float)iz;
        float wx0 = 1.f-fx, wx1 = fx, wy0 = 1.f-fy, wy1 = fy,
              wz0 = 1.f-fz, wz1 = fz;

        const float* gp = grid + ((size_t)(ix*RG + iy)*RG + iz)*13;

        float vals[13];
        #pragma unroll
        for (int c = 0; c < 13; c++) vals[c] = 0.f;
        float c0a[8];
        #pragma unroll
        for (int cc = 0; cc < 8; cc++) {
            int dx = cc >> 2, dy = (cc >> 1) & 1, dz = cc & 1;
            const float* p = gp + dx*OX + dy*OY + dz*OZ;
            float w = (dx ? wx1 : wx0) * (dy ? wy1 : wy0) * (dz ? wz1 : wz0);
            float v0 = __ldg(p);
            c0a[cc] = v0;
            vals[0] = fmaf(w, v0, vals[0]);
            #pragma unroll
            for (int c = 1; c < 13; c++) vals[c] = fmaf(w, __ldg(p + c), vals[c]);
        }
        float gx = 63.5f*( wy0*wz0*(c0a[4]-c0a[0]) + wy0*wz1*(c0a[5]-c0a[1])
                         + wy1*wz0*(c0a[6]-c0a[2]) + wy1*wz1*(c0a[7]-c0a[3]) );
        float gy = 63.5f*( wx0*wz0*(c0a[2]-c0a[0]) + wx0*wz1*(c0a[3]-c0a[1])
                         + wx1*wz0*(c0a[6]-c0a[4]) + wx1*wz1*(c0a[7]-c0a[5]) );
        float gz = 63.5f*( wx0*wy0*(c0a[1]-c0a[0]) + wx0*wy1*(c0a[3]-c0a[2])
                         + wx1*wy0*(c0a[5]-c0a[4]) + wx1*wy1*(c0a[7]-c0a[6]) );

        g_inT[ 0*NPTS + i] = px;
        g_inT[ 1*NPTS + i] = py;
        g_inT[ 2*NPTS + i] = pz;
        g_inT[ 3*NPTS + i] = gx;
        g_inT[ 4*NPTS + i] = gy;
        g_inT[ 5*NPTS + i] = gz;
        g_inT[ 6*NPTS + i] = __ldg(&viewdirs[3*r+0]);
        g_inT[ 7*NPTS + i] = __ldg(&viewdirs[3*r+1]);
        g_inT[ 8*NPTS + i] = __ldg(&viewdirs[3*r+2]);
        #pragma unroll
        for (int l = 0; l < NLAT; l++)
            g_inT[(9+l)*NPTS + i] = vals[1+l];
        g_inT[21*NPTS + i] = vals[0];
    }
}

// ---------------------------------------------------------------------------
// Kernel M: MLP only, 2 points per thread, inputs via coalesced LDG.
// ---------------------------------------------------------------------------
__global__ __launch_bounds__(128, 5)
void mlp_kernel(const float* __restrict__ W1,
                const float* __restrict__ W2,
                const float* __restrict__ b2)
{
    __shared__ __align__(16) float sW[NROW*NHID];  // rows 0-8 raw, 9-20 folded
    __shared__ __align__(16) float sW2t[3*NHID];   // [c][j]
    __shared__ __align__(16) float sb1[NHID];
    __shared__ float sb2[4];

    for (int i = threadIdx.x; i < 9*NHID; i += blockDim.x) sW[i] = W1[i];
    for (int i = threadIdx.x; i < NLAT*NHID; i += blockDim.x)
        sW[9*NHID + i] = g_W1eff[i];
    for (int i = threadIdx.x; i < NHID; i += blockDim.x) sb1[i] = g_b1eff[i];
    for (int i = threadIdx.x; i < NHID*3; i += blockDim.x) {
        int j = i / 3, c = i - 3*j;
        sW2t[c*NHID + j] = W2[i];
    }
    if (threadIdx.x < 3) sb2[threadIdx.x] = b2[threadIdx.x];
    __syncthreads();

    int total  = g_total;
    int gid    = blockIdx.x*blockDim.x + threadIdx.x;
    int stride = gridDim.x*blockDim.x;

    for (int t = gid; 2*t < total; t += stride) {
        int iA = 2*t;
        bool hasB = (2*t + 1 < total);
        int iB = hasB ? (2*t + 1) : iA;

        float inA[NROW], inB[NROW];
        #pragma unroll
        for (int k = 0; k < NROW; k++) {
            inA[k] = __ldg(&g_inT[k*NPTS + iA]);
            inB[k] = __ldg(&g_inT[k*NPTS + iB]);
        }
        float sdfA = __ldg(&g_inT[21*NPTS + iA]);
        float sdfB = __ldg(&g_inT[21*NPTS + iB]);

        float oA0=0.f, oA1=0.f, oA2=0.f, oB0=0.f, oB1=0.f, oB2=0.f;
        #pragma unroll 2
        for (int j = 0; j < NHID; j += 4) {
            float4 bj = *(const float4*)&sb1[j];
            float4 aA = bj, aB = bj;
            #pragma unroll
            for (int k = 0; k < NROW; k++) {
                float4 w = *(const float4*)&sW[k*NHID + j];
                float hA = inA[k], hB = inB[k];
                aA.x = fmaf(hA, w.x, aA.x);  aB.x = fmaf(hB, w.x, aB.x);
                aA.y = fmaf(hA, w.y, aA.y);  aB.y = fmaf(hB, w.y, aB.y);
                aA.z = fmaf(hA, w.z, aA.z);  aB.z = fmaf(hB, w.z, aB.z);
                aA.w = fmaf(hA, w.w, aA.w);  aB.w = fmaf(hB, w.w, aB.w);
            }
            aA.x = fmaxf(aA.x, 0.f); aA.y = fmaxf(aA.y, 0.f);
            aA.z = fmaxf(aA.z, 0.f); aA.w = fmaxf(aA.w, 0.f);
            aB.x = fmaxf(aB.x, 0.f); aB.y = fmaxf(aB.y, 0.f);
            aB.z = fmaxf(aB.z, 0.f); aB.w = fmaxf(aB.w, 0.f);
            float4 wa = *(const float4*)&sW2t[0*NHID + j];
            float4 wb = *(const float4*)&sW2t[1*NHID + j];
            float4 wc = *(const float4*)&sW2t[2*NHID + j];
            oA0 = fmaf(aA.x,wa.x, fmaf(aA.y,wa.y, fmaf(aA.z,wa.z, fmaf(aA.w,wa.w, oA0))));
            oA1 = fmaf(aA.x,wb.x, fmaf(aA.y,wb.y, fmaf(aA.z,wb.z, fmaf(aA.w,wb.w, oA1))));
            oA2 = fmaf(aA.x,wc.x, fmaf(aA.y,wc.y, fmaf(aA.z,wc.z, fmaf(aA.w,wc.w, oA2))));
            oB0 = fmaf(aB.x,wa.x, fmaf(aB.y,wa.y, fmaf(aB.z,wa.z, fmaf(aB.w,wa.w, oB0))));
            oB1 = fmaf(aB.x,wb.x, fmaf(aB.y,wb.y, fmaf(aB.z,wb.z, fmaf(aB.w,wb.w, oB1))));
            oB2 = fmaf(aB.x,wc.x, fmaf(aB.y,wc.y, fmaf(aB.z,wc.z, fmaf(aB.w,wc.w, oB2))));
        }
        oA0 += sb2[0]; oA1 += sb2[1]; oA2 += sb2[2];
        oB0 += sb2[0]; oB1 += sb2[1]; oB2 += sb2[2];

        int pa = g_act_list[iA];
        g_rgbs[(pa >> 9)*NS + (pa & 511)] =
            make_float4(1.f/(1.f + expf(-oA0)),
                        1.f/(1.f + expf(-oA1)),
                        1.f/(1.f + expf(-oA2)), sdfA);
        if (hasB) {
            int pb = g_act_list[iB];
            g_rgbs[(pb >> 9)*NS + (pb & 511)] =
                make_float4(1.f/(1.f + expf(-oB0)),
                            1.f/(1.f + expf(-oB1)),
                            1.f/(1.f + expf(-oB2)), sdfB);
        }
    }
}

// ---------------------------------------------------------------------------
// Kernel B: per-ray transmittance scan. One warp (=one block) per ray.
// ---------------------------------------------------------------------------
__global__ __launch_bounds__(32)
void ray_kernel(const float* __restrict__ rays_d,
                const float* __restrict__ beta_p,
                float* __restrict__ out)
{
    int ray  = blockIdx.x;
    int lane = threadIdx.x;

    float be    = fabsf(__ldg(beta_p)) + 1e-4f;
    float inv_b = 1.0f / be;
    float d0 = __ldg(&rays_d[3*ray+0]);
    float d1 = __ldg(&rays_d[3*ray+1]);
    float d2 = __ldg(&rays_d[3*ray+2]);
    float dn = sqrtf(d0*d0 + d1*d1 + d2*d2);

    int slo = g_slo[ray];
    int scnt = g_scnt[ray];
    int shi = slo + scnt;

    const float4* vp = g_rgbs + (size_t)ray*NS;
    const float dist = 3.0f/499.0f;

    float4 v[16];
    #pragma unroll
    for (int c = 0; c < 16; c++) {
        int s = c*32 + lane;
        bool in = (scnt > 0) & (s >= slo) & (s < shi) & (s < NS);
        v[c] = in ? __ldg(&vp[s]) : make_float4(0.f, 0.f, 0.f, 100.f);
    }

    float fe[16];
    #pragma unroll
    for (int c = 0; c < 16; c++) {
        float sdf = v[c].w;
        float as  = fabsf(sdf);
        float sg  = (sdf > 0.f) ? 1.f : ((sdf < 0.f) ? -1.f : 0.f);
        float dens = inv_b * (0.5f + 0.5f*sg*expm1f(-as*inv_b));
        fe[c] = dist * dens;
    }

    float inc[16];
    #pragma unroll
    for (int c = 0; c < 16; c++) {
        float x = fe[c];
        #pragma unroll
        for (int o = 1; o < 32; o <<= 1) {
            float n = __shfl_up_sync(0xffffffffu, x, o);
            if (lane >= o) x += n;
        }
        inc[c] = x;
    }

    float carry = 0.f, r0 = 0.f, r1 = 0.f, r2 = 0.f, dep = 0.f;
    #pragma unroll
    for (int c = 0; c < 16; c++) {
        float excl  = carry + (inc[c] - fe[c]);
        float T     = expf(-excl);
        float alpha = 1.f - expf(-fe[c]);
        float w     = alpha * T;
        int   s     = c*32 + lane;
        float zs    = 0.5f + 3.0f*((float)s * (1.0f/499.0f));
        if (s < NS) {
            r0  += w * v[c].x;
            r1  += w * v[c].y;
            r2  += w * v[c].z;
            dep += w * zs * dn;
        }
        carry += __shfl_sync(0xffffffffu, inc[c], 31);
    }

    #pragma unroll
    for (int o = 16; o > 0; o >>= 1) {
        r0  += __shfl_xor_sync(0xffffffffu, r0,  o);
        r1  += __shfl_xor_sync(0xffffffffu, r1,  o);
        r2  += __shfl_xor_sync(0xffffffffu, r2,  o);
        dep += __shfl_xor_sync(0xffffffffu, dep, o);
    }
    if (lane == 0) {
        out[3*ray+0]     = r0;
        out[3*ray+1]     = r1;
        out[3*ray+2]     = r2;
        out[3*NB_ + ray] = dep;
    }
}

// ---------------------------------------------------------------------------
extern "C" void kernel_launch(void* const* d_in, const int* in_sizes, int n_in,
                              void* d_out, int out_size)
{
    const float* rays_o   = (const float*)d_in[0];
    const float* rays_d   = (const float*)d_in[1];
    const float* viewdirs = (const float*)d_in[2];
    const float* grid     = (const float*)d_in[3];
    const float* Wf       = (const float*)d_in[4];
    const float* bf       = (const float*)d_in[5];
    const float* W1       = (const float*)d_in[6];
    const float* b1       = (const float*)d_in[7];
    const float* W2       = (const float*)d_in[8];
    const float* b2       = (const float*)d_in[9];
    const float* beta     = (const float*)d_in[10];

    // ncu captures our 0-based launch index 3 -> mlp_kernel there.
    prep_kernel<<<1, 256>>>(Wf, bf, W1, b1);                 // resets g_total
    interval_kernel<<<NB_/8, 256>>>(rays_o, rays_d);
    trilerp_kernel<<<1184, 128>>>(rays_o, rays_d, viewdirs, grid);
    mlp_kernel<<<740, 128>>>(W1, W2, b2);
    ray_kernel<<<NB_, 32>>>(rays_d, beta, (float*)d_out);
}